// round 6
// baseline (speedup 1.0000x reference)
#include <cuda_runtime.h>
#include <cstdint>

// ---------------- model constants ----------------
#define TT     3
#define LL     3
#define EE     50000
#define NN     1000000
#define RRR    200
#define NRELC  401
#define HHH    256
#define TOPKC  1000
#define BBB    8
#define K32    32
#define NB_LSTM 96
#define NBH    148

// ---------------- device scratch ----------------
__device__ float g_x[EE * K32];
__device__ float g_s[EE * K32];
__device__ unsigned char g_actb[EE];
__device__ float g_w[TT * NRELC * K32];
__device__ float g_h[6 * 4 * BBB * HHH];
__device__ float g_th[K32];
__device__ float g_sums[TT][K32];
__device__ int   g_cnt[1];
__device__ unsigned long long g_list[2 * NN];
__device__ unsigned g_hist8[24 * 256];
__device__ unsigned g_selb[24];
__device__ unsigned g_need[24];
__device__ int      g_ccnt[24];
__device__ unsigned g_cand[24 * EE];
__device__ unsigned g_barw = 0;

__device__ __forceinline__ float sigf(float x) { return 1.0f / (1.0f + expf(-x)); }
__device__ __forceinline__ float dot4(float4 a, float4 b) {
    return a.x * b.x + a.y * b.y + a.z * b.z + a.w * b.w;
}

// Replay-safe grid barrier: packed word = gen*256 + count. Every barrier adds
// exactly 256, so gen is monotone across graph replays. Both-side fences:
// release (writes flushed) before arrive, acquire (+L1 invalidate) after.
template <int NB>
__device__ __forceinline__ void gbar() {
    __threadfence();
    __syncthreads();
    if (threadIdx.x == 0) {
        unsigned old = atomicAdd(&g_barw, 1u);
        unsigned gen = old >> 8;
        if ((old & 255u) == NB - 1) {
            atomicAdd(&g_barw, 256u - NB);
        } else {
            while (((*(volatile unsigned*)&g_barw) >> 8) == gen) __nanosleep(64);
        }
    }
    __syncthreads();
    __threadfence();
}

// ---------------- fused LSTM: pre-projection + 4 recurrent steps ----------------
__global__ __launch_bounds__(256, 1) void lstm_fused_kernel(
    const int* __restrict__ input_r, const float* __restrict__ emb,
    const float* __restrict__ Wih_f, const float* __restrict__ bih_f, const float* __restrict__ bhh_f,
    const float* __restrict__ Wih_b, const float* __restrict__ bih_b, const float* __restrict__ bhh_b,
    const float* __restrict__ Whh_f, const float* __restrict__ Whh_b)
{
    int blk = blockIdx.x;
    int ld = blk >> 4, cg = blk & 15;
    int l = ld >> 1, dir = ld & 1;
    const float* Wih = (dir ? Wih_b : Wih_f) + l * 1024 * HHH;
    const float* Whh = (dir ? Whh_b : Whh_f) + l * 1024 * HHH;
    const float* bih = (dir ? bih_b : bih_f) + l * 1024;
    const float* bhh = (dir ? bhh_b : bhh_f) + l * 1024;

    __shared__ float sv[9][HHH];
    __shared__ float pre_s[4][8][64];
    __shared__ float sh[8][HHH];
    __shared__ float sc[8][16];
    __shared__ float sacc_s[4][16][8];
    __shared__ int sr[8];

    int tid = threadIdx.x, lane = tid & 31, warp = tid >> 5;
    int gate = warp & 3, kc8 = (warp >> 2) * 8;

    // housekeeping (consumed only by later kernel)
    if (blk == 0) {
        for (int i = tid; i < TT * NRELC * K32; i += 256) g_w[i] = 0.0f;
        if (tid < TT * K32) ((float*)g_sums)[tid] = 0.0f;
        if (tid < K32) g_th[tid] = __uint_as_float(0x7F800000u);   // +inf
        for (int i = tid; i < 24 * 256; i += 256) g_hist8[i] = 0u;
    }

    if (tid < 8) sr[tid] = input_r[tid];
    __syncthreads();
    for (int i = tid; i < 9 * HHH; i += 256) {
        int v = i >> 8, c = i & 255;
        int rs = (v < 8) ? sr[v] : (NRELC - 1);
        sv[v][c] = emb[rs * HHH + c];
    }
    __syncthreads();

    float4 w[16];
    #pragma unroll
    for (int r = 0; r < 8; r++) {
        int j = gate * 256 + cg * 16 + kc8 + r;
        const float4* w4 = (const float4*)(Wih + j * HHH);
        w[2 * r] = w4[lane * 2]; w[2 * r + 1] = w4[lane * 2 + 1];
    }
    #pragma unroll
    for (int r = 0; r < 8; r++) {
        int j = gate * 256 + cg * 16 + kc8 + r;
        float acc[9];
        #pragma unroll
        for (int v = 0; v < 9; v++) {
            const float4* s4 = (const float4*)sv[v];
            acc[v] = dot4(w[2 * r], s4[lane * 2]) + dot4(w[2 * r + 1], s4[lane * 2 + 1]);
        }
        #pragma unroll
        for (int v = 0; v < 9; v++)
            #pragma unroll
            for (int o = 16; o; o >>= 1) acc[v] += __shfl_down_sync(0xFFFFFFFFu, acc[v], o);
        if (lane == 0) {
            float bb = bih[j] + bhh[j];
            int row = gate * 16 + kc8 + r;
            #pragma unroll
            for (int t = 0; t < 4; t++)
                #pragma unroll
                for (int b = 0; b < 8; b++) {
                    int v = dir ? ((t == 0) ? 8 : b) : ((t < 3) ? b : 8);
                    pre_s[t][b][row] = acc[v] + bb;
                }
        }
    }
    #pragma unroll
    for (int r = 0; r < 8; r++) {
        int j = gate * 256 + cg * 16 + kc8 + r;
        const float4* w4 = (const float4*)(Whh + j * HHH);
        w[2 * r] = w4[lane * 2]; w[2 * r + 1] = w4[lane * 2 + 1];
    }
    __syncthreads();

    for (int t = 0; t < 4; t++) {
        if (t > 0) {
            const float* hp = &g_h[((ld * 4 + (t - 1)) * 8) * HHH];
            for (int i = tid; i < 8 * HHH; i += 256) ((float*)sh)[i] = hp[i];
            __syncthreads();
        }
        #pragma unroll
        for (int r = 0; r < 8; r++) {
            float acc[8];
            #pragma unroll
            for (int b = 0; b < 8; b++) {
                if (t > 0) {
                    const float4* h4 = (const float4*)sh[b];
                    acc[b] = dot4(w[2 * r], h4[lane * 2]) + dot4(w[2 * r + 1], h4[lane * 2 + 1]);
                } else acc[b] = 0.0f;
            }
            #pragma unroll
            for (int b = 0; b < 8; b++)
                #pragma unroll
                for (int o = 16; o; o >>= 1) acc[b] += __shfl_down_sync(0xFFFFFFFFu, acc[b], o);
            if (lane == 0) {
                int kc = kc8 + r;
                #pragma unroll
                for (int b = 0; b < 8; b++)
                    sacc_s[gate][kc][b] = acc[b] + pre_s[t][b][gate * 16 + kc];
            }
        }
        __syncthreads();
        if (tid < 128) {
            int kc = tid >> 3, b = tid & 7;
            float gi = sacc_s[0][kc][b], gf = sacc_s[1][kc][b];
            float gg = sacc_s[2][kc][b], go = sacc_s[3][kc][b];
            float cp = (t > 0) ? sc[b][kc] : 0.0f;
            float c = sigf(gf) * cp + sigf(gi) * tanhf(gg);
            float h = sigf(go) * tanhf(c);
            sc[b][kc] = c;
            g_h[((ld * 4 + t) * 8 + b) * HHH + cg * 16 + kc] = h;
        }
        if (t < 3) gbar<NB_LSTM>();
    }
}

// ---------------- persistent hops kernel: wlin + 3 hops + out, 2nd launch ----------------
__global__ __launch_bounds__(256, 1) void hops_kernel(
    const int* __restrict__ input_x,
    const int* __restrict__ heads, const int* __restrict__ tails,
    const int* __restrict__ tails2, const int* __restrict__ rels,
    const float* __restrict__ linW, const float* __restrict__ linb,
    float* __restrict__ out)
{
    int tid = threadIdx.x, lane = tid & 31, warp = tid >> 5;
    int blk = blockIdx.x;
    int gwarp = blk * 8 + warp;
    const int NWRP = NBH * 8;
    const int TOTT = NBH * 256;
    int gtid = blk * 256 + tid;

    __shared__ float s_rnn[2 * HHH];
    __shared__ float s_logit[NRELC];
    __shared__ float s_red[256];
    __shared__ unsigned s_hist[24][257];
    __shared__ unsigned s_h[256], s_scan[256];
    __shared__ unsigned s_pref, s_need_s;
    __shared__ unsigned s_ssel[24];
    __shared__ float s_smf[8][32];
    __shared__ int s_xs[8];

    // ======== phase: wlin (blocks 0..71 -> one (t,l,b) each) ========
    if (blk < 72) {
        int t = blk / 24, l = (blk % 24) / 8, b = blk % 8;
        const float* hf = &g_h[(((l * 2 + 0) * 4 + t) * BBB + b) * HHH];
        const float* hb = &g_h[(((l * 2 + 1) * 4 + (3 - t)) * BBB + b) * HHH];
        for (int i = tid; i < HHH; i += 256) { s_rnn[i] = hf[i]; s_rnn[HHH + i] = hb[i]; }
        __syncthreads();
        const float4* r4 = (const float4*)s_rnn;
        for (int n = tid; n < NRELC; n += 256) {
            const float4* w4 = (const float4*)(linW + n * 2 * HHH);
            float acc = 0.0f;
            for (int kk = 0; kk < (2 * HHH) / 4; kk++) acc += dot4(w4[kk], r4[kk]);
            s_logit[n] = acc + linb[n];
        }
        __syncthreads();
        float m = -1e30f;
        for (int n = tid; n < NRELC; n += 256) m = fmaxf(m, s_logit[n]);
        s_red[tid] = m; __syncthreads();
        for (int o = 128; o; o >>= 1) { if (tid < o) s_red[tid] = fmaxf(s_red[tid], s_red[tid + o]); __syncthreads(); }
        m = s_red[0]; __syncthreads();
        float ssum = 0.0f;
        for (int n = tid; n < NRELC; n += 256) {
            float e = expf((s_logit[n] - m) / 10.0f);
            s_logit[n] = e; ssum += e;
        }
        s_red[tid] = ssum; __syncthreads();
        for (int o = 128; o; o >>= 1) { if (tid < o) s_red[tid] += s_red[tid + o]; __syncthreads(); }
        ssum = s_red[0];
        int k = b * 3 + l;
        for (int n = tid; n < NRELC; n += 256)
            g_w[(t * NRELC + n) * K32 + k] = s_logit[n] / ssum;
    }
    gbar<NBH>();

    // ======== phase: buildx0 ========
    {
        if (tid < 8) s_xs[tid] = input_x[tid];
        if (gtid == 0) atomicExch(&g_cnt[0], 0);
        __syncthreads();
        float wid = g_w[(NRELC - 1) * K32 + lane];
        int bsel = (lane < 24) ? (lane / 3) : 0;
        float sacc = 0.0f;
        for (int e = gwarp; e < EE; e += NWRP) {
            float x = (lane < 24 && s_xs[bsel] == e) ? 1.0f : 0.0f;
            g_x[e * K32 + lane] = x;
            float s = wid * x;
            g_s[e * K32 + lane] = s;
            sacc += s;
            unsigned nz = __ballot_sync(0xFFFFFFFFu, x != 0.0f);
            if (lane == 0) g_actb[e] = nz ? 1 : 0;
        }
        s_smf[warp][lane] = sacc; __syncthreads();
        if (tid < 32) {
            float s = 0.0f;
            #pragma unroll
            for (int w2 = 0; w2 < 8; w2++) s += s_smf[w2][tid];
            if (s != 0.0f) atomicAdd(&g_sums[0][tid], s);
        }
    }
    gbar<NBH>();

    // ======== hop loop ========
    for (int t = 0; t < TT; t++) {
        // ---- compact: int4 loads, warp-scan aggregation ----
        {
            const int4* h4p  = (const int4*)heads;
            const int4* t4p  = (const int4*)tails2;
            const int4* tl4p = (const int4*)tails;
            const int4* r4p  = (const int4*)rels;
            const int nq = NN / 4;
            const int iters = (nq + TOTT - 1) / TOTT;
            for (int it = 0; it < iters; it++) {
                int q = gtid + it * TOTT;
                bool valid = q < nq;
                int4 h4 = {0,0,0,0}, t4 = {0,0,0,0};
                int a0 = 0, a1 = 0, a2 = 0, a3 = 0, b0 = 0, b1 = 0, b2 = 0, b3 = 0;
                int cnt = 0;
                if (valid) {
                    h4 = h4p[q]; t4 = t4p[q];
                    a0 = g_actb[h4.x]; a1 = g_actb[h4.y]; a2 = g_actb[h4.z]; a3 = g_actb[h4.w];
                    b0 = g_actb[t4.x]; b1 = g_actb[t4.y]; b2 = g_actb[t4.z]; b3 = g_actb[t4.w];
                    cnt = a0 + a1 + a2 + a3 + b0 + b1 + b2 + b3;
                }
                unsigned any = __ballot_sync(0xFFFFFFFFu, cnt > 0);
                if (!any) continue;
                int pre = cnt;
                #pragma unroll
                for (int o = 1; o < 32; o <<= 1) {
                    int v = __shfl_up_sync(0xFFFFFFFFu, pre, o);
                    if (lane >= o) pre += v;
                }
                int total = __shfl_sync(0xFFFFFFFFu, pre, 31);
                int base;
                if (lane == 31) base = atomicAdd(&g_cnt[0], total);
                base = __shfl_sync(0xFFFFFFFFu, base, 31);
                int off = base + pre - cnt;
                if (cnt) {
                    int4 r4v = r4p[q];
                    int4 tl4 = tl4p[q];
                    if (a0) g_list[off++] = (((unsigned long long)r4v.x) << 32) | ((unsigned)tl4.x << 16) | (unsigned)h4.x;
                    if (b0) g_list[off++] = (((unsigned long long)(r4v.x + RRR)) << 32) | ((unsigned)h4.x << 16) | (unsigned)t4.x;
                    if (a1) g_list[off++] = (((unsigned long long)r4v.y) << 32) | ((unsigned)tl4.y << 16) | (unsigned)h4.y;
                    if (b1) g_list[off++] = (((unsigned long long)(r4v.y + RRR)) << 32) | ((unsigned)h4.y << 16) | (unsigned)t4.y;
                    if (a2) g_list[off++] = (((unsigned long long)r4v.z) << 32) | ((unsigned)tl4.z << 16) | (unsigned)h4.z;
                    if (b2) g_list[off++] = (((unsigned long long)(r4v.z + RRR)) << 32) | ((unsigned)h4.z << 16) | (unsigned)t4.z;
                    if (a3) g_list[off++] = (((unsigned long long)r4v.w) << 32) | ((unsigned)tl4.w << 16) | (unsigned)h4.w;
                    if (b3) g_list[off++] = (((unsigned long long)(r4v.w + RRR)) << 32) | ((unsigned)h4.w << 16) | (unsigned)t4.w;
                }
            }
        }
        gbar<NBH>();

        // ---- propagate over packed list + sums ----
        {
            const float* wt = &g_w[t * NRELC * K32];
            int cnt = g_cnt[0];
            float sacc = 0.0f;
            for (int j0 = gwarp * 6; j0 < cnt; j0 += NWRP * 6) {
                int n = min(6, cnt - j0);
                unsigned long long e[6];
                #pragma unroll
                for (int u = 0; u < 6; u++) if (u < n) e[u] = g_list[j0 + u];
                float xv[6], wv[6];
                #pragma unroll
                for (int u = 0; u < 6; u++) if (u < n) {
                    int src = (int)(e[u] & 0xFFFFu);
                    int rel = (int)(e[u] >> 32);
                    xv[u] = g_x[src * K32 + lane];
                    wv[u] = wt[rel * K32 + lane];
                }
                #pragma unroll
                for (int u = 0; u < 6; u++) if (u < n) {
                    int dst = (int)((e[u] >> 16) & 0xFFFFu);
                    float mm = xv[u] * wv[u];
                    sacc += mm;
                    if (mm != 0.0f) atomicAdd(&g_s[dst * K32 + lane], mm);
                }
            }
            __syncthreads();
            s_smf[warp][lane] = sacc; __syncthreads();
            if (tid < 32) {
                float s = 0.0f;
                #pragma unroll
                for (int w2 = 0; w2 < 8; w2++) s += s_smf[w2][tid];
                if (s != 0.0f) atomicAdd(&g_sums[t][tid], s);
            }
        }
        gbar<NBH>();
        if (t == TT - 1) break;

        // ---- select A: 8-bit histogram ----
        {
            for (int i = tid; i < 24 * 257; i += 256) ((unsigned*)s_hist)[i] = 0u;
            __syncthreads();
            int q = tid & 7, eo = tid >> 3;
            int base = blk * 338;
            int lim = min(base + 338, EE);
            if (q < 6) {
                for (int e = base + eo; e < lim; e += 32) {
                    float4 v = *(const float4*)&g_s[e * K32 + q * 4];
                    #pragma unroll
                    for (int c = 0; c < 4; c++) {
                        unsigned u = __float_as_uint(c == 0 ? v.x : c == 1 ? v.y : c == 2 ? v.z : v.w);
                        if (u == 0x80000000u) u = 0;
                        atomicAdd(&s_hist[q * 4 + c][u >> 24], 1u);
                    }
                }
            }
            __syncthreads();
            for (int i = tid; i < 24 * 256; i += 256) {
                unsigned v = s_hist[i >> 8][i & 255];
                if (v) atomicAdd(&g_hist8[i], v);
            }
        }
        gbar<NBH>();

        // ---- pick top byte (blocks 0..23) ----
        if (blk < 24) {
            int k = blk;
            unsigned v = g_hist8[k * 256 + tid];
            s_h[tid] = v; s_scan[tid] = v;
            __syncthreads();
            for (int o = 1; o < 256; o <<= 1) {
                unsigned add = (tid + o < 256) ? s_scan[tid + o] : 0u;
                __syncthreads();
                s_scan[tid] += add;
                __syncthreads();
            }
            unsigned cumIncl = s_scan[tid];
            unsigned cumAbove = cumIncl - s_h[tid];
            if (cumIncl >= TOPKC && cumAbove < TOPKC) {
                g_need[k] = TOPKC - cumAbove;
                g_selb[k] = (unsigned)tid;
            }
            g_hist8[k * 256 + tid] = 0u;
            if (tid == 0) g_ccnt[k] = 0;
        }
        gbar<NBH>();

        // ---- candidate compaction (single pass, nonzero matching top byte) ----
        {
            if (tid < 24) s_ssel[tid] = g_selb[tid];
            __syncthreads();
            int q = tid & 7, eo = tid >> 3;
            int base = blk * 338;
            int lim = min(base + 338, EE);
            if (q < 6) {
                for (int e = base + eo; e < lim; e += 32) {
                    float4 v = *(const float4*)&g_s[e * K32 + q * 4];
                    #pragma unroll
                    for (int c = 0; c < 4; c++) {
                        unsigned u = __float_as_uint(c == 0 ? v.x : c == 1 ? v.y : c == 2 ? v.z : v.w);
                        if (u == 0x80000000u) u = 0;
                        int k = q * 4 + c;
                        if (u != 0 && (u >> 24) == s_ssel[k]) {
                            int off = atomicAdd(&g_ccnt[k], 1);
                            g_cand[k * EE + off] = u;
                        }
                    }
                }
            }
        }
        gbar<NBH>();

        // ---- finish selection on low 24 bits (blocks 0..23) ----
        if (blk < 24) {
            int k = blk;
            int cnt = g_ccnt[k];
            unsigned need = g_need[k];
            unsigned selb = g_selb[k];
            if ((unsigned)cnt < need) {
                if (tid == 0) g_th[k] = 0.0f;
            } else {
                unsigned pref = 0;
                for (int p = 2; p >= 0; p--) {
                    s_h[tid] = 0u;
                    __syncthreads();
                    for (int i = tid; i < cnt; i += 256) {
                        unsigned u = g_cand[k * EE + i] & 0xFFFFFFu;
                        bool ok = (p == 2) || ((u >> (8 * p + 8)) == pref);
                        if (ok) atomicAdd(&s_h[(u >> (8 * p)) & 255u], 1u);
                    }
                    __syncthreads();
                    s_scan[tid] = s_h[tid];
                    __syncthreads();
                    for (int o = 1; o < 256; o <<= 1) {
                        unsigned add = (tid + o < 256) ? s_scan[tid + o] : 0u;
                        __syncthreads();
                        s_scan[tid] += add;
                        __syncthreads();
                    }
                    unsigned cumIncl = s_scan[tid];
                    unsigned cumAbove = cumIncl - s_h[tid];
                    if (cumIncl >= need && cumAbove < need) {
                        s_pref = (pref << 8) | (unsigned)tid;
                        s_need_s = need - cumAbove;
                    }
                    __syncthreads();
                    pref = s_pref; need = s_need_s;
                    __syncthreads();
                }
                if (tid == 0) g_th[k] = __uint_as_float((selb << 24) | pref);
            }
        }
        gbar<NBH>();

        // ---- buildx for hop t+1 ----
        {
            if (gtid == 0) atomicExch(&g_cnt[0], 0);
            float wid = g_w[((t + 1) * NRELC + (NRELC - 1)) * K32 + lane];
            float th = g_th[lane];
            float denom = fmaxf(g_sums[t][lane], 1e-7f);
            float sacc = 0.0f;
            for (int e = gwarp; e < EE; e += NWRP) {
                float v = g_s[e * K32 + lane];
                float x = (v >= th) ? (v / denom) : 0.0f;
                g_x[e * K32 + lane] = x;
                float s = wid * x;
                g_s[e * K32 + lane] = s;
                sacc += s;
                unsigned nz = __ballot_sync(0xFFFFFFFFu, x != 0.0f);
                if (lane == 0) g_actb[e] = nz ? 1 : 0;
            }
            __syncthreads();
            s_smf[warp][lane] = sacc; __syncthreads();
            if (tid < 32) {
                float s = 0.0f;
                #pragma unroll
                for (int w2 = 0; w2 < 8; w2++) s += s_smf[w2][tid];
                if (s != 0.0f) atomicAdd(&g_sums[t + 1][tid], s);
            }
        }
        gbar<NBH>();
    }

    // ======== phase: output ========
    {
        for (int idx = gtid; idx < BBB * EE; idx += TOTT) {
            int b = idx / EE, e = idx - b * EE;
            float acc = 0.0f;
            #pragma unroll
            for (int l = 0; l < LL; l++) {
                int k = b * 3 + l;
                acc += g_s[e * K32 + k] / fmaxf(g_sums[TT - 1][k], 1e-7f);
            }
            out[idx] = acc;
        }
    }
}

// ---------------- launch: 2 kernels total ----------------
extern "C" void kernel_launch(void* const* d_in, const int* in_sizes, int n_in,
                              void* d_out, int out_size) {
    const int*   input_x  = (const int*)d_in[0];
    const int*   input_r  = (const int*)d_in[1];
    const int*   e2triple = (const int*)d_in[2];
    const int*   triple2e = (const int*)d_in[3];
    const int*   r2triple = (const int*)d_in[4];
    const float* emb      = (const float*)d_in[5];
    const float* Wih_f    = (const float*)d_in[6];
    const float* Whh_f    = (const float*)d_in[7];
    const float* bih_f    = (const float*)d_in[8];
    const float* bhh_f    = (const float*)d_in[9];
    const float* Wih_b    = (const float*)d_in[10];
    const float* Whh_b    = (const float*)d_in[11];
    const float* bih_b    = (const float*)d_in[12];
    const float* bhh_b    = (const float*)d_in[13];
    const float* linW     = (const float*)d_in[14];
    const float* linb     = (const float*)d_in[15];

    const int* heads  = e2triple;
    const int* tails2 = e2triple + 2 * NN;
    const int* tails  = triple2e + NN;
    const int* rels   = r2triple;

    lstm_fused_kernel<<<NB_LSTM, 256>>>(input_r, emb, Wih_f, bih_f, bhh_f,
                                        Wih_b, bih_b, bhh_b, Whh_f, Whh_b);
    hops_kernel<<<NBH, 256>>>(input_x, heads, tails, tails2, rels,
                              linW, linb, (float*)d_out);
}

// round 7
// speedup vs baseline: 1.8543x; 1.8543x over previous
#include <cuda_runtime.h>
#include <cstdint>

// ---------------- model constants ----------------
#define TT     3
#define LL     3
#define EE     50000
#define NN     1000000
#define RRR    200
#define NRELC  401
#define HHH    256
#define TOPKC  1000
#define BBB    8
#define K32    32
#define NB_LSTM 96

// ---------------- device scratch ----------------
__device__ float g_x[EE * K32];
__device__ float g_s[EE * K32];
__device__ unsigned char g_actb[EE];
__device__ float g_w[TT * NRELC * K32];
__device__ float g_h[6 * 4 * BBB * HHH];
__device__ float g_th[K32];
__device__ float g_sums[TT][K32];
__device__ int   g_cnt[1];
__device__ unsigned long long g_list[2 * NN];
__device__ int      g_ccnt[24];
__device__ unsigned g_cand[24 * EE];
__device__ unsigned g_barw = 0;

__device__ __forceinline__ float sigf(float x) { return 1.0f / (1.0f + expf(-x)); }
__device__ __forceinline__ float dot4(float4 a, float4 b) {
    return a.x * b.x + a.y * b.y + a.z * b.z + a.w * b.w;
}

// Replay-safe grid barrier for the LSTM kernel only.
template <int NB>
__device__ __forceinline__ void gbar() {
    __threadfence();
    __syncthreads();
    if (threadIdx.x == 0) {
        unsigned old = atomicAdd(&g_barw, 1u);
        unsigned gen = old >> 8;
        if ((old & 255u) == NB - 1) {
            atomicAdd(&g_barw, 256u - NB);
        } else {
            while (((*(volatile unsigned*)&g_barw) >> 8) == gen) __nanosleep(64);
        }
    }
    __syncthreads();
    __threadfence();
}

// ---------------- fused LSTM: pre-projection + 4 recurrent steps ----------------
__global__ __launch_bounds__(256, 1) void lstm_fused_kernel(
    const int* __restrict__ input_r, const float* __restrict__ emb,
    const float* __restrict__ Wih_f, const float* __restrict__ bih_f, const float* __restrict__ bhh_f,
    const float* __restrict__ Wih_b, const float* __restrict__ bih_b, const float* __restrict__ bhh_b,
    const float* __restrict__ Whh_f, const float* __restrict__ Whh_b)
{
    int blk = blockIdx.x;
    int ld = blk >> 4, cg = blk & 15;
    int l = ld >> 1, dir = ld & 1;
    const float* Wih = (dir ? Wih_b : Wih_f) + l * 1024 * HHH;
    const float* Whh = (dir ? Whh_b : Whh_f) + l * 1024 * HHH;
    const float* bih = (dir ? bih_b : bih_f) + l * 1024;
    const float* bhh = (dir ? bhh_b : bhh_f) + l * 1024;

    __shared__ float sv[9][HHH];
    __shared__ float pre_s[4][8][64];
    __shared__ float sh[8][HHH];
    __shared__ float sc[8][16];
    __shared__ float sacc_s[4][16][8];
    __shared__ int sr[8];

    int tid = threadIdx.x, lane = tid & 31, warp = tid >> 5;
    int gate = warp & 3, kc8 = (warp >> 2) * 8;

    // housekeeping (consumed only by later kernels)
    if (blk == 0) {
        for (int i = tid; i < TT * NRELC * K32; i += 256) g_w[i] = 0.0f;
        if (tid < TT * K32) ((float*)g_sums)[tid] = 0.0f;
    }

    if (tid < 8) sr[tid] = input_r[tid];
    __syncthreads();
    for (int i = tid; i < 9 * HHH; i += 256) {
        int v = i >> 8, c = i & 255;
        int rs = (v < 8) ? sr[v] : (NRELC - 1);
        sv[v][c] = emb[rs * HHH + c];
    }
    __syncthreads();

    float4 w[16];
    #pragma unroll
    for (int r = 0; r < 8; r++) {
        int j = gate * 256 + cg * 16 + kc8 + r;
        const float4* w4 = (const float4*)(Wih + j * HHH);
        w[2 * r] = w4[lane * 2]; w[2 * r + 1] = w4[lane * 2 + 1];
    }
    #pragma unroll
    for (int r = 0; r < 8; r++) {
        int j = gate * 256 + cg * 16 + kc8 + r;
        float acc[9];
        #pragma unroll
        for (int v = 0; v < 9; v++) {
            const float4* s4 = (const float4*)sv[v];
            acc[v] = dot4(w[2 * r], s4[lane * 2]) + dot4(w[2 * r + 1], s4[lane * 2 + 1]);
        }
        #pragma unroll
        for (int v = 0; v < 9; v++)
            #pragma unroll
            for (int o = 16; o; o >>= 1) acc[v] += __shfl_down_sync(0xFFFFFFFFu, acc[v], o);
        if (lane == 0) {
            float bb = bih[j] + bhh[j];
            int row = gate * 16 + kc8 + r;
            #pragma unroll
            for (int t = 0; t < 4; t++)
                #pragma unroll
                for (int b = 0; b < 8; b++) {
                    int v = dir ? ((t == 0) ? 8 : b) : ((t < 3) ? b : 8);
                    pre_s[t][b][row] = acc[v] + bb;
                }
        }
    }
    #pragma unroll
    for (int r = 0; r < 8; r++) {
        int j = gate * 256 + cg * 16 + kc8 + r;
        const float4* w4 = (const float4*)(Whh + j * HHH);
        w[2 * r] = w4[lane * 2]; w[2 * r + 1] = w4[lane * 2 + 1];
    }
    __syncthreads();

    for (int t = 0; t < 4; t++) {
        if (t > 0) {
            const float* hp = &g_h[((ld * 4 + (t - 1)) * 8) * HHH];
            for (int i = tid; i < 8 * HHH; i += 256) ((float*)sh)[i] = hp[i];
            __syncthreads();
        }
        #pragma unroll
        for (int r = 0; r < 8; r++) {
            float acc[8];
            #pragma unroll
            for (int b = 0; b < 8; b++) {
                if (t > 0) {
                    const float4* h4 = (const float4*)sh[b];
                    acc[b] = dot4(w[2 * r], h4[lane * 2]) + dot4(w[2 * r + 1], h4[lane * 2 + 1]);
                } else acc[b] = 0.0f;
            }
            #pragma unroll
            for (int b = 0; b < 8; b++)
                #pragma unroll
                for (int o = 16; o; o >>= 1) acc[b] += __shfl_down_sync(0xFFFFFFFFu, acc[b], o);
            if (lane == 0) {
                int kc = kc8 + r;
                #pragma unroll
                for (int b = 0; b < 8; b++)
                    sacc_s[gate][kc][b] = acc[b] + pre_s[t][b][gate * 16 + kc];
            }
        }
        __syncthreads();
        if (tid < 128) {
            int kc = tid >> 3, b = tid & 7;
            float gi = sacc_s[0][kc][b], gf = sacc_s[1][kc][b];
            float gg = sacc_s[2][kc][b], go = sacc_s[3][kc][b];
            float cp = (t > 0) ? sc[b][kc] : 0.0f;
            float c = sigf(gf) * cp + sigf(gi) * tanhf(gg);
            float h = sigf(go) * tanhf(c);
            sc[b][kc] = c;
            g_h[((ld * 4 + t) * 8 + b) * HHH + cg * 16 + kc] = h;
        }
        if (t < 3) gbar<NB_LSTM>();
    }
}

// ---------------- linear + softmax -> relation weights ----------------
__global__ void wlin_kernel(const float* __restrict__ linW, const float* __restrict__ linb) {
    int t = blockIdx.x / 3, l = blockIdx.x % 3, b = blockIdx.y;
    __shared__ float rnn[2 * HHH];
    __shared__ float logit[NRELC];
    __shared__ float red[128];
    int tid = threadIdx.x;

    const float* hf = &g_h[(((l * 2 + 0) * 4 + t) * BBB + b) * HHH];
    const float* hb = &g_h[(((l * 2 + 1) * 4 + (3 - t)) * BBB + b) * HHH];
    for (int i = tid; i < HHH; i += 128) { rnn[i] = hf[i]; rnn[HHH + i] = hb[i]; }
    __syncthreads();

    const float4* r4 = (const float4*)rnn;
    for (int n = tid; n < NRELC; n += 128) {
        const float4* w4 = (const float4*)(linW + n * 2 * HHH);
        float acc = 0.0f;
        for (int kk = 0; kk < (2 * HHH) / 4; kk++) acc += dot4(w4[kk], r4[kk]);
        logit[n] = acc + linb[n];
    }
    __syncthreads();

    float m = -1e30f;
    for (int n = tid; n < NRELC; n += 128) m = fmaxf(m, logit[n]);
    red[tid] = m; __syncthreads();
    for (int o = 64; o; o >>= 1) { if (tid < o) red[tid] = fmaxf(red[tid], red[tid + o]); __syncthreads(); }
    m = red[0]; __syncthreads();

    float s = 0.0f;
    for (int n = tid; n < NRELC; n += 128) {
        float e = expf((logit[n] - m) / 10.0f);
        logit[n] = e; s += e;
    }
    red[tid] = s; __syncthreads();
    for (int o = 64; o; o >>= 1) { if (tid < o) red[tid] += red[tid + o]; __syncthreads(); }
    s = red[0];

    int k = b * 3 + l;
    for (int n = tid; n < NRELC; n += 128)
        g_w[(t * NRELC + n) * K32 + k] = logit[n] / s;
}

// ---------------- x builders (fused identity-init + activity + sums) ----------------
__global__ void buildx0_kernel(const int* __restrict__ input_x) {
    __shared__ int xs[BBB];
    __shared__ float sm[8][32];
    if (threadIdx.x < BBB) xs[threadIdx.x] = input_x[threadIdx.x];
    __syncthreads();
    int gtid = blockIdx.x * blockDim.x + threadIdx.x;
    if (gtid == 0) g_cnt[0] = 0;
    int lane = threadIdx.x & 31;
    int warp = gtid >> 5;
    int nw = (gridDim.x * blockDim.x) >> 5;
    float wid = g_w[(NRELC - 1) * K32 + lane];
    int bsel = (lane < 24) ? (lane / 3) : 0;
    float sacc = 0.0f;
    for (int e = warp; e < EE; e += nw) {
        float x = (lane < 24 && xs[bsel] == e) ? 1.0f : 0.0f;
        g_x[e * K32 + lane] = x;
        float s = wid * x;
        g_s[e * K32 + lane] = s;
        sacc += s;
        unsigned nz = __ballot_sync(0xFFFFFFFFu, x != 0.0f);
        if (lane == 0) g_actb[e] = nz ? 1 : 0;
    }
    sm[threadIdx.x >> 5][lane] = sacc;
    __syncthreads();
    if (threadIdx.x < 32) {
        float s = 0.0f;
        #pragma unroll
        for (int w = 0; w < 8; w++) s += sm[w][threadIdx.x];
        if (s != 0.0f) atomicAdd(&g_sums[0][threadIdx.x], s);
    }
}

__global__ void buildx_kernel(int t) {
    __shared__ float sm[8][32];
    int gtid = blockIdx.x * blockDim.x + threadIdx.x;
    if (gtid == 0) g_cnt[0] = 0;
    int lane = threadIdx.x & 31;
    int warp = gtid >> 5;
    int nw = (gridDim.x * blockDim.x) >> 5;
    float wid = g_w[(t * NRELC + (NRELC - 1)) * K32 + lane];
    float th = g_th[lane];
    float denom = fmaxf(g_sums[t - 1][lane], 1e-7f);
    float sacc = 0.0f;
    for (int e = warp; e < EE; e += nw) {
        float v = g_s[e * K32 + lane];
        float x = (v >= th) ? (v / denom) : 0.0f;
        g_x[e * K32 + lane] = x;
        float s = wid * x;
        g_s[e * K32 + lane] = s;
        sacc += s;
        unsigned nz = __ballot_sync(0xFFFFFFFFu, x != 0.0f);
        if (lane == 0) g_actb[e] = nz ? 1 : 0;
    }
    sm[threadIdx.x >> 5][lane] = sacc;
    __syncthreads();
    if (threadIdx.x < 32) {
        float s = 0.0f;
        #pragma unroll
        for (int w = 0; w < 8; w++) s += sm[w][threadIdx.x];
        if (s != 0.0f) atomicAdd(&g_sums[t][threadIdx.x], s);
    }
}

// ---------------- compact: int4 loads, warp-scan aggregation ----------------
__global__ void compact_kernel(const int* __restrict__ heads, const int* __restrict__ tails,
                               const int* __restrict__ tails2, const int* __restrict__ rels) {
    int gtid = blockIdx.x * blockDim.x + threadIdx.x;
    if (gtid < 24) g_ccnt[gtid] = 0;    // reset for this hop's select
    int lane = threadIdx.x & 31;
    int tot = gridDim.x * blockDim.x;
    const int4* h4p  = (const int4*)heads;
    const int4* t4p  = (const int4*)tails2;
    const int4* tl4p = (const int4*)tails;
    const int4* r4p  = (const int4*)rels;
    const int nq = NN / 4;
    const int iters = (nq + tot - 1) / tot;

    for (int it = 0; it < iters; it++) {
        int q = gtid + it * tot;
        bool valid = q < nq;
        int4 h4 = {0,0,0,0}, t4 = {0,0,0,0};
        int a0 = 0, a1 = 0, a2 = 0, a3 = 0, b0 = 0, b1 = 0, b2 = 0, b3 = 0;
        int cnt = 0;
        if (valid) {
            h4 = h4p[q]; t4 = t4p[q];
            a0 = g_actb[h4.x]; a1 = g_actb[h4.y]; a2 = g_actb[h4.z]; a3 = g_actb[h4.w];
            b0 = g_actb[t4.x]; b1 = g_actb[t4.y]; b2 = g_actb[t4.z]; b3 = g_actb[t4.w];
            cnt = a0 + a1 + a2 + a3 + b0 + b1 + b2 + b3;
        }
        unsigned any = __ballot_sync(0xFFFFFFFFu, cnt > 0);
        if (!any) continue;
        int pre = cnt;
        #pragma unroll
        for (int o = 1; o < 32; o <<= 1) {
            int v = __shfl_up_sync(0xFFFFFFFFu, pre, o);
            if (lane >= o) pre += v;
        }
        int total = __shfl_sync(0xFFFFFFFFu, pre, 31);
        int base;
        if (lane == 31) base = atomicAdd(&g_cnt[0], total);
        base = __shfl_sync(0xFFFFFFFFu, base, 31);
        int off = base + pre - cnt;
        if (cnt) {
            int4 r4v = r4p[q];
            int4 tl4 = tl4p[q];
            if (a0) g_list[off++] = (((unsigned long long)r4v.x) << 32) | ((unsigned)tl4.x << 16) | (unsigned)h4.x;
            if (b0) g_list[off++] = (((unsigned long long)(r4v.x + RRR)) << 32) | ((unsigned)h4.x << 16) | (unsigned)t4.x;
            if (a1) g_list[off++] = (((unsigned long long)r4v.y) << 32) | ((unsigned)tl4.y << 16) | (unsigned)h4.y;
            if (b1) g_list[off++] = (((unsigned long long)(r4v.y + RRR)) << 32) | ((unsigned)h4.y << 16) | (unsigned)t4.y;
            if (a2) g_list[off++] = (((unsigned long long)r4v.z) << 32) | ((unsigned)tl4.z << 16) | (unsigned)h4.z;
            if (b2) g_list[off++] = (((unsigned long long)(r4v.z + RRR)) << 32) | ((unsigned)h4.z << 16) | (unsigned)t4.z;
            if (a3) g_list[off++] = (((unsigned long long)r4v.w) << 32) | ((unsigned)tl4.w << 16) | (unsigned)h4.w;
            if (b3) g_list[off++] = (((unsigned long long)(r4v.w + RRR)) << 32) | ((unsigned)h4.w << 16) | (unsigned)t4.w;
        }
    }
}

// ---------------- propagate over packed list + accumulate sums ----------------
__global__ void prop_kernel(int t) {
    __shared__ float sm[8][32];
    int lane = threadIdx.x & 31;
    int warp = (blockIdx.x * blockDim.x + threadIdx.x) >> 5;
    int nw = (gridDim.x * blockDim.x) >> 5;
    const float* wt = &g_w[t * NRELC * K32];
    int cnt = g_cnt[0];
    float sacc = 0.0f;

    for (int j0 = warp * 6; j0 < cnt; j0 += nw * 6) {
        int n = min(6, cnt - j0);
        unsigned long long e[6];
        #pragma unroll
        for (int u = 0; u < 6; u++) if (u < n) e[u] = g_list[j0 + u];
        float xv[6], wv[6];
        #pragma unroll
        for (int u = 0; u < 6; u++) if (u < n) {
            int src = (int)(e[u] & 0xFFFFu);
            int rel = (int)(e[u] >> 32);
            xv[u] = g_x[src * K32 + lane];
            wv[u] = wt[rel * K32 + lane];
        }
        #pragma unroll
        for (int u = 0; u < 6; u++) if (u < n) {
            int dst = (int)((e[u] >> 16) & 0xFFFFu);
            float mm = xv[u] * wv[u];
            sacc += mm;
            if (mm != 0.0f) atomicAdd(&g_s[dst * K32 + lane], mm);
        }
    }
    sm[threadIdx.x >> 5][lane] = sacc;
    __syncthreads();
    if (threadIdx.x < 32) {
        float s = 0.0f;
        #pragma unroll
        for (int w = 0; w < 8; w++) s += sm[w][threadIdx.x];
        if (s != 0.0f) atomicAdd(&g_sums[t][threadIdx.x], s);
    }
}

// ---------------- nonzero compaction for select: one coalesced pass ----------------
__global__ void nzc_kernel() {
    int gtid = blockIdx.x * blockDim.x + threadIdx.x;
    int stride = gridDim.x * blockDim.x;
    for (int i = gtid; i < EE * K32; i += stride) {
        int k = i & 31;
        if (k < 24) {
            float v = g_s[i];
            if (v != 0.0f) {
                int off = atomicAdd(&g_ccnt[k], 1);
                g_cand[k * EE + off] = __float_as_uint(v);
            }
        }
    }
}

// ---------------- exact top-k threshold from candidates: 4x8-bit radix ----------------
__global__ void sel_kernel() {
    int k = blockIdx.x, tid = threadIdx.x;
    int cnt = g_ccnt[k];
    __shared__ unsigned s_h[256], s_scan[256];
    __shared__ unsigned s_pref, s_need;

    if (cnt < TOPKC) {           // kth largest is 0 (values are nonnegative)
        if (tid == 0) g_th[k] = 0.0f;
        return;
    }
    unsigned pref = 0, need = TOPKC;
    const unsigned* cand = &g_cand[k * EE];
    for (int p = 3; p >= 0; p--) {
        s_h[tid] = 0u;
        __syncthreads();
        for (int i = tid; i < cnt; i += 256) {
            unsigned u = cand[i];
            bool ok = (p == 3) || ((u >> (8 * p + 8)) == pref);
            if (ok) atomicAdd(&s_h[(u >> (8 * p)) & 255u], 1u);
        }
        __syncthreads();
        s_scan[tid] = s_h[tid];
        __syncthreads();
        for (int o = 1; o < 256; o <<= 1) {
            unsigned add = (tid + o < 256) ? s_scan[tid + o] : 0u;
            __syncthreads();
            s_scan[tid] += add;
            __syncthreads();
        }
        unsigned cumIncl = s_scan[tid];
        unsigned cumAbove = cumIncl - s_h[tid];
        if (cumIncl >= need && cumAbove < need) {
            s_pref = (pref << 8) | (unsigned)tid;
            s_need = need - cumAbove;
        }
        __syncthreads();
        pref = s_pref; need = s_need;
        __syncthreads();
    }
    if (tid == 0) g_th[k] = __uint_as_float(pref);
}

// ---------------- final output ----------------
__global__ void out_kernel(float* __restrict__ out) {
    int stride = gridDim.x * blockDim.x;
    for (int idx = blockIdx.x * blockDim.x + threadIdx.x; idx < BBB * EE; idx += stride) {
        int b = idx / EE, e = idx - b * EE;
        float acc = 0.0f;
        #pragma unroll
        for (int l = 0; l < LL; l++) {
            int k = b * 3 + l;
            acc += g_s[e * K32 + k] / fmaxf(g_sums[TT - 1][k], 1e-7f);
        }
        out[idx] = acc;
    }
}

// ---------------- launch ----------------
extern "C" void kernel_launch(void* const* d_in, const int* in_sizes, int n_in,
                              void* d_out, int out_size) {
    const int*   input_x  = (const int*)d_in[0];
    const int*   input_r  = (const int*)d_in[1];
    const int*   e2triple = (const int*)d_in[2];
    const int*   triple2e = (const int*)d_in[3];
    const int*   r2triple = (const int*)d_in[4];
    const float* emb      = (const float*)d_in[5];
    const float* Wih_f    = (const float*)d_in[6];
    const float* Whh_f    = (const float*)d_in[7];
    const float* bih_f    = (const float*)d_in[8];
    const float* bhh_f    = (const float*)d_in[9];
    const float* Wih_b    = (const float*)d_in[10];
    const float* Whh_b    = (const float*)d_in[11];
    const float* bih_b    = (const float*)d_in[12];
    const float* bhh_b    = (const float*)d_in[13];
    const float* linW     = (const float*)d_in[14];
    const float* linb     = (const float*)d_in[15];

    const int* heads  = e2triple;
    const int* tails2 = e2triple + 2 * NN;
    const int* tails  = triple2e + NN;
    const int* rels   = r2triple;

    lstm_fused_kernel<<<NB_LSTM, 256>>>(input_r, emb, Wih_f, bih_f, bhh_f,
                                        Wih_b, bih_b, bhh_b, Whh_f, Whh_b);
    wlin_kernel<<<dim3(9, 8), 128>>>(linW, linb);

    for (int t = 0; t < TT; t++) {
        if (t == 0) {
            buildx0_kernel<<<512, 256>>>(input_x);
        } else {
            nzc_kernel<<<512, 256>>>();
            sel_kernel<<<24, 256>>>();
            buildx_kernel<<<512, 256>>>(t);
        }
        compact_kernel<<<1024, 256>>>(heads, tails, tails2, rels);
        prop_kernel<<<1024, 256>>>(t);
    }

    out_kernel<<<512, 256>>>((float*)d_out);
}